// round 1
// baseline (speedup 1.0000x reference)
#include <cuda_runtime.h>
#include <math.h>

#define BB 128
#define NN 4096
#define DD 64
#define SS 7
#define HH 128
#define NUM_ITERS 3
#define EPSV 1e-8f
#define LN_EPS 1e-5f
#define SCALE 0.125f   // 64^-0.5

#define TILE 128
#define PAD 68

// persistent scratch (no allocation allowed)
__device__ float g_slots[BB*SS*DD];
__device__ float g_qt[BB*SS*DD];
__device__ float g_u[BB*SS*DD];
__device__ float g_den[BB*SS];

// ---------------------------------------------------------------------------
// slots = mu + exp(log_sigma) * noise
__global__ void k_init_slots(const float* __restrict__ noise,
                             const float* __restrict__ mu,
                             const float* __restrict__ logsig) {
    int i = blockIdx.x * blockDim.x + threadIdx.x;
    if (i < BB*SS*DD) {
        int d = i & 63;
        g_slots[i] = mu[d] + expf(logsig[d]) * noise[i];
    }
}

// ---------------------------------------------------------------------------
// per batch: s=LN(slots); q=(s@Wq.T)*scale; qt=q@Wk ; also zero accumulators
// grid = B, block = 224 (warp per slot)
__global__ void k_compute_q(const float* __restrict__ Wq,
                            const float* __restrict__ Wk,
                            const float* __restrict__ lnw,
                            const float* __restrict__ lnb) {
    int b = blockIdx.x;
    int s = threadIdx.x >> 5;
    int lane = threadIdx.x & 31;
    __shared__ float sn[SS][64];
    __shared__ float q[SS][64];

    const float* sl = g_slots + (b*SS + s)*DD;
    float v0 = sl[lane], v1 = sl[lane+32];
    float sum = v0 + v1, sq = v0*v0 + v1*v1;
    #pragma unroll
    for (int o = 16; o; o >>= 1) {
        sum += __shfl_xor_sync(0xffffffffu, sum, o);
        sq  += __shfl_xor_sync(0xffffffffu, sq,  o);
    }
    float mean = sum * (1.f/64.f);
    float var  = sq  * (1.f/64.f) - mean*mean;
    float rstd = rsqrtf(var + LN_EPS);
    sn[s][lane]    = (v0 - mean)*rstd*lnw[lane]    + lnb[lane];
    sn[s][lane+32] = (v1 - mean)*rstd*lnw[lane+32] + lnb[lane+32];
    __syncwarp();

    float a0 = 0.f, a1 = 0.f;
    #pragma unroll 8
    for (int e = 0; e < 64; e++) {
        float x = sn[s][e];
        a0 += x * Wq[lane*64 + e];
        a1 += x * Wq[(lane+32)*64 + e];
    }
    q[s][lane]    = a0 * SCALE;
    q[s][lane+32] = a1 * SCALE;
    __syncwarp();

    float t0 = 0.f, t1 = 0.f;
    #pragma unroll 8
    for (int d = 0; d < 64; d++) {
        float qq = q[s][d];
        t0 += qq * Wk[d*64 + lane];
        t1 += qq * Wk[d*64 + lane+32];
    }
    int base = (b*SS + s)*DD;
    g_qt[base + lane]    = t0;
    g_qt[base + lane+32] = t1;
    // zero accumulators for this iteration
    g_u[base + lane]    = 0.f;
    g_u[base + lane+32] = 0.f;
    if (lane == 0) g_den[b*SS + s] = 0.f;
}

// ---------------------------------------------------------------------------
// main pass: LN(inputs tile) -> logits vs qt -> softmax+EPS -> accumulate
// u[s,e] and den[s]. grid = (N/TILE, B), block = 128.
__global__ void __launch_bounds__(128) k_attn(const float* __restrict__ inputs,
                                              const float* __restrict__ lnw_g,
                                              const float* __restrict__ lnb_g) {
    int b = blockIdx.y, tile = blockIdx.x;
    int tid = threadIdx.x;
    __shared__ __align__(16) float xs[TILE*PAD];
    __shared__ __align__(16) float qts[SS][64];
    __shared__ float ps[TILE][8];
    __shared__ __align__(16) float lnw[64];
    __shared__ __align__(16) float lnb[64];

    if (tid < 64) { lnw[tid] = lnw_g[tid]; lnb[tid] = lnb_g[tid]; }
    for (int i = tid; i < SS*64; i += 128)
        qts[i >> 6][i & 63] = g_qt[b*SS*64 + i];

    const float* src = inputs + ((size_t)b*NN + (size_t)tile*TILE) * DD;
    #pragma unroll
    for (int k = 0; k < TILE*64/128; k++) {
        int i = tid + k*128;
        xs[(i >> 6)*PAD + (i & 63)] = src[i];
    }
    __syncthreads();

    // phase A: per-token LN + logits + softmax
    {
        float4* row = (float4*)(xs + tid*PAD);
        float sum = 0.f, sq = 0.f;
        #pragma unroll
        for (int k = 0; k < 16; k++) {
            float4 v = row[k];
            sum += v.x + v.y + v.z + v.w;
            sq  += v.x*v.x + v.y*v.y + v.z*v.z + v.w*v.w;
        }
        float mean = sum * (1.f/64.f);
        float var  = sq  * (1.f/64.f) - mean*mean;
        float rstd = rsqrtf(var + LN_EPS);

        float lg[SS];
        #pragma unroll
        for (int s = 0; s < SS; s++) lg[s] = 0.f;
        const float4* w4 = (const float4*)lnw;
        const float4* b4 = (const float4*)lnb;
        #pragma unroll
        for (int k = 0; k < 16; k++) {
            float4 v = row[k], w = w4[k], bb = b4[k], n;
            n.x = (v.x - mean)*rstd*w.x + bb.x;
            n.y = (v.y - mean)*rstd*w.y + bb.y;
            n.z = (v.z - mean)*rstd*w.z + bb.z;
            n.w = (v.w - mean)*rstd*w.w + bb.w;
            row[k] = n;
            #pragma unroll
            for (int s = 0; s < SS; s++) {
                float4 qv = ((const float4*)qts[s])[k];
                lg[s] += n.x*qv.x + n.y*qv.y + n.z*qv.z + n.w*qv.w;
            }
        }
        float mx = lg[0];
        #pragma unroll
        for (int s = 1; s < SS; s++) mx = fmaxf(mx, lg[s]);
        float ex[SS], tot = 0.f;
        #pragma unroll
        for (int s = 0; s < SS; s++) { ex[s] = expf(lg[s] - mx); tot += ex[s]; }
        float inv = 1.f / tot;
        #pragma unroll
        for (int s = 0; s < SS; s++) ps[tid][s] = ex[s]*inv + EPSV;
    }
    __syncthreads();

    // phase B: partial u[s][e] = sum_t p[t][s]*xn[t][e], den[s] = sum_t p
    if (tid < 112) {
        int s = tid >> 4, e4 = tid & 15;
        float4 acc = make_float4(0.f, 0.f, 0.f, 0.f);
        #pragma unroll 8
        for (int t = 0; t < TILE; t++) {
            float p = ps[t][s];
            float4 v = *(const float4*)(xs + t*PAD + e4*4);
            acc.x += p*v.x; acc.y += p*v.y; acc.z += p*v.z; acc.w += p*v.w;
        }
        float* up = g_u + (b*SS + s)*DD + e4*4;
        atomicAdd(up + 0, acc.x);
        atomicAdd(up + 1, acc.y);
        atomicAdd(up + 2, acc.z);
        atomicAdd(up + 3, acc.w);
    } else if (tid < 119) {
        int s = tid - 112;
        float dacc = 0.f;
        #pragma unroll 8
        for (int t = 0; t < TILE; t++) dacc += ps[t][s];
        atomicAdd(&g_den[b*SS + s], dacc);
    }
}

// ---------------------------------------------------------------------------
// finalize: updates = (u@Wv.T)/den ; GRU ; LN ; MLP ; write new slots
// grid = B, block = 224 (warp per slot)
__global__ void k_finalize(const float* __restrict__ Wv,
                           const float* __restrict__ W_ih,
                           const float* __restrict__ W_hh,
                           const float* __restrict__ b_ih,
                           const float* __restrict__ b_hh,
                           const float* __restrict__ W1,
                           const float* __restrict__ b1,
                           const float* __restrict__ W2,
                           const float* __restrict__ b2,
                           const float* __restrict__ lnw,
                           const float* __restrict__ lnb,
                           float* __restrict__ out, int write_out) {
    int b = blockIdx.x;
    int s = threadIdx.x >> 5;
    int lane = threadIdx.x & 31;

    __shared__ float um[SS][64];
    __shared__ float upd[SS][64];
    __shared__ float prevs[SS][64];
    __shared__ float gi[SS][192];
    __shared__ float gh[SS][192];
    __shared__ float newsl[SS][64];
    __shared__ float mln[SS][64];
    __shared__ float h1[SS][128];

    int base = (b*SS + s)*DD;
    um[s][lane]    = g_u[base + lane];
    um[s][lane+32] = g_u[base + lane+32];
    float invden = 1.f / g_den[b*SS + s];
    float prev0 = g_slots[base + lane], prev1 = g_slots[base + lane+32];
    prevs[s][lane] = prev0; prevs[s][lane+32] = prev1;
    __syncwarp();

    // updates
    float a0 = 0.f, a1 = 0.f;
    #pragma unroll 8
    for (int e = 0; e < 64; e++) {
        float u = um[s][e];
        a0 += u * Wv[lane*64 + e];
        a1 += u * Wv[(lane+32)*64 + e];
    }
    upd[s][lane]    = a0 * invden;
    upd[s][lane+32] = a1 * invden;
    __syncwarp();

    // GRU gates: gi = upd@W_ih.T + b_ih ; gh = prev@W_hh.T + b_hh
    #pragma unroll
    for (int k = 0; k < 6; k++) {
        int j = lane + 32*k;
        float ai = b_ih[j], ah = b_hh[j];
        #pragma unroll 8
        for (int e = 0; e < 64; e++) {
            ai += upd[s][e]   * W_ih[j*64 + e];
            ah += prevs[s][e] * W_hh[j*64 + e];
        }
        gi[s][j] = ai; gh[s][j] = ah;
    }
    __syncwarp();

    float ns0, ns1;
    {
        float r0 = 1.f / (1.f + expf(-(gi[s][lane]      + gh[s][lane])));
        float z0 = 1.f / (1.f + expf(-(gi[s][64+lane]   + gh[s][64+lane])));
        float n0 = tanhf(gi[s][128+lane] + r0*gh[s][128+lane]);
        ns0 = (1.f - z0)*n0 + z0*prev0;
        float r1 = 1.f / (1.f + expf(-(gi[s][lane+32]    + gh[s][lane+32])));
        float z1 = 1.f / (1.f + expf(-(gi[s][96+lane]    + gh[s][96+lane])));
        float n1 = tanhf(gi[s][160+lane] + r1*gh[s][160+lane]);
        ns1 = (1.f - z1)*n1 + z1*prev1;
    }
    newsl[s][lane] = ns0; newsl[s][lane+32] = ns1;

    // LN for MLP
    float sum = ns0 + ns1, sq = ns0*ns0 + ns1*ns1;
    #pragma unroll
    for (int o = 16; o; o >>= 1) {
        sum += __shfl_xor_sync(0xffffffffu, sum, o);
        sq  += __shfl_xor_sync(0xffffffffu, sq,  o);
    }
    float mean = sum * (1.f/64.f);
    float var  = sq  * (1.f/64.f) - mean*mean;
    float rstd = rsqrtf(var + LN_EPS);
    mln[s][lane]    = (ns0 - mean)*rstd*lnw[lane]    + lnb[lane];
    mln[s][lane+32] = (ns1 - mean)*rstd*lnw[lane+32] + lnb[lane+32];
    __syncwarp();

    // h1 = relu(m@W1.T + b1)
    #pragma unroll
    for (int k = 0; k < 4; k++) {
        int j = lane + 32*k;
        float acc = b1[j];
        #pragma unroll 8
        for (int e = 0; e < 64; e++) acc += mln[s][e] * W1[j*64 + e];
        h1[s][j] = fmaxf(acc, 0.f);
    }
    __syncwarp();

    // out = newslots + h1@W2.T + b2
    float o0 = b2[lane], o1 = b2[lane+32];
    #pragma unroll 8
    for (int j = 0; j < 128; j++) {
        float h = h1[s][j];
        o0 += h * W2[lane*128 + j];
        o1 += h * W2[(lane+32)*128 + j];
    }
    float r0 = ns0 + o0, r1 = ns1 + o1;
    g_slots[base + lane]    = r0;
    g_slots[base + lane+32] = r1;
    if (write_out) {
        out[base + lane]    = r0;
        out[base + lane+32] = r1;
    }
}

// ---------------------------------------------------------------------------
extern "C" void kernel_launch(void* const* d_in, const int* in_sizes, int n_in,
                              void* d_out, int out_size) {
    const float* inputs     = (const float*)d_in[0];
    const float* noise      = (const float*)d_in[1];
    const float* ln_in_w    = (const float*)d_in[2];
    const float* ln_in_b    = (const float*)d_in[3];
    const float* ln_slots_w = (const float*)d_in[4];
    const float* ln_slots_b = (const float*)d_in[5];
    const float* ln_mlp_w   = (const float*)d_in[6];
    const float* ln_mlp_b   = (const float*)d_in[7];
    const float* mu         = (const float*)d_in[8];
    const float* logsig     = (const float*)d_in[9];
    const float* Wq         = (const float*)d_in[10];
    const float* Wk         = (const float*)d_in[11];
    const float* Wv         = (const float*)d_in[12];
    const float* W_ih       = (const float*)d_in[13];
    const float* W_hh       = (const float*)d_in[14];
    const float* b_ih       = (const float*)d_in[15];
    const float* b_hh       = (const float*)d_in[16];
    const float* W1         = (const float*)d_in[17];
    const float* b1         = (const float*)d_in[18];
    const float* W2         = (const float*)d_in[19];
    const float* b2         = (const float*)d_in[20];
    float* out = (float*)d_out;

    k_init_slots<<<(BB*SS*DD + 255)/256, 256>>>(noise, mu, logsig);
    for (int it = 0; it < NUM_ITERS; it++) {
        k_compute_q<<<BB, 224>>>(Wq, Wk, ln_slots_w, ln_slots_b);
        dim3 grid(NN/TILE, BB);
        k_attn<<<grid, 128>>>(inputs, ln_in_w, ln_in_b);
        k_finalize<<<BB, 224>>>(Wv, W_ih, W_hh, b_ih, b_hh,
                                W1, b1, W2, b2, ln_mlp_w, ln_mlp_b,
                                out, it == NUM_ITERS - 1 ? 1 : 0);
    }
}

// round 2
// speedup vs baseline: 2.2742x; 2.2742x over previous
#include <cuda_runtime.h>
#include <math.h>

#define BB 128
#define NN 4096
#define DD 64
#define SS 7
#define HH 128
#define NUM_ITERS 3
#define EPSV 1e-8f
#define LN_EPS 1e-5f
#define SCALE 0.125f   // 64^-0.5

#define TILE 128
#define PAD 68

// persistent scratch (no allocation allowed)
__device__ float g_slots[BB*SS*DD];
__device__ float g_qt[BB*SS*DD];
__device__ float g_u[BB*SS*DD];
__device__ float g_den[BB*SS];
__device__ float g_M[DD*DD];      // scale * Wq^T @ Wk   [e][t]
__device__ float g_C[3*DD*DD];    // W_ih @ Wv           [j][e]

// ---------------------------------------------------------------------------
// slots = mu + exp(log_sigma) * noise
__global__ void k_init_slots(const float* __restrict__ noise,
                             const float* __restrict__ mu,
                             const float* __restrict__ logsig) {
    int i = blockIdx.x * blockDim.x + threadIdx.x;
    if (i < BB*SS*DD) {
        int d = i & 63;
        g_slots[i] = mu[d] + expf(logsig[d]) * noise[i];
    }
}

// ---------------------------------------------------------------------------
// Precompute M = scale * Wq^T @ Wk  and  C = W_ih @ Wv.
// grid = 64 blocks x 256 threads. Blocks 0..15 -> M (4096 outs), 16..63 -> C.
__global__ void k_precomp(const float* __restrict__ Wq,
                          const float* __restrict__ Wk,
                          const float* __restrict__ W_ih,
                          const float* __restrict__ Wv) {
    int bi = blockIdx.x, t = threadIdx.x;
    if (bi < 16) {
        int o = bi*256 + t;
        int e = o >> 6, tc = o & 63;
        float acc = 0.f;
        #pragma unroll 8
        for (int d = 0; d < 64; d++)
            acc += Wq[d*64 + e] * Wk[d*64 + tc];
        g_M[e*64 + tc] = acc * SCALE;
    } else {
        int o = (bi-16)*256 + t;
        int j = o >> 6, e = o & 63;
        float acc = 0.f;
        #pragma unroll 8
        for (int h = 0; h < 64; h++)
            acc += W_ih[j*64 + h] * Wv[h*64 + e];
        g_C[j*64 + e] = acc;
    }
}

// ---------------------------------------------------------------------------
// Initial q: LN(slots) @ M -> g_qt ; zero accumulators.
// grid = B, block = 256 (warps 0..6 do LN of slot s)
__global__ void k_q0(const float* __restrict__ lnw,
                     const float* __restrict__ lnb) {
    int b = blockIdx.x;
    int tid = threadIdx.x;
    int w = tid >> 5, lane = tid & 31;
    __shared__ float sn[SS*64];

    if (w < SS) {
        const float* sl = g_slots + (b*SS + w)*DD;
        float v0 = sl[lane], v1 = sl[lane+32];
        float sum = v0 + v1, sq = v0*v0 + v1*v1;
        #pragma unroll
        for (int o = 16; o; o >>= 1) {
            sum += __shfl_xor_sync(0xffffffffu, sum, o);
            sq  += __shfl_xor_sync(0xffffffffu, sq,  o);
        }
        float mean = sum * (1.f/64.f);
        float var  = sq  * (1.f/64.f) - mean*mean;
        float rstd = rsqrtf(var + LN_EPS);
        sn[w*64 + lane]    = (v0 - mean)*rstd*lnw[lane]    + lnb[lane];
        sn[w*64 + lane+32] = (v1 - mean)*rstd*lnw[lane+32] + lnb[lane+32];
    }
    // zero accumulators
    for (int i = tid; i < SS*64; i += 256) g_u[b*SS*64 + i] = 0.f;
    if (tid < SS) g_den[b*SS + tid] = 0.f;
    __syncthreads();

    for (int i = tid; i < SS*64; i += 256) {
        int s = i >> 6, tc = i & 63;
        float acc = 0.f;
        #pragma unroll 8
        for (int e = 0; e < 64; e++)
            acc += sn[s*64 + e] * g_M[e*64 + tc];
        g_qt[b*SS*64 + i] = acc;
    }
}

// ---------------------------------------------------------------------------
// main pass: LN(inputs tile) -> logits vs qt -> softmax+EPS -> accumulate
// u[s,e] and den[s]. grid = (N/TILE, B), block = 128.
__global__ void __launch_bounds__(128) k_attn(const float* __restrict__ inputs,
                                              const float* __restrict__ lnw_g,
                                              const float* __restrict__ lnb_g) {
    int b = blockIdx.y, tile = blockIdx.x;
    int tid = threadIdx.x;
    __shared__ __align__(16) float xs[TILE*PAD];
    __shared__ __align__(16) float qts[SS][64];
    __shared__ float ps[TILE][8];
    __shared__ __align__(16) float lnw[64];
    __shared__ __align__(16) float lnb[64];

    if (tid < 64) { lnw[tid] = lnw_g[tid]; lnb[tid] = lnb_g[tid]; }
    for (int i = tid; i < SS*64; i += 128)
        qts[i >> 6][i & 63] = g_qt[b*SS*64 + i];

    const float* src = inputs + ((size_t)b*NN + (size_t)tile*TILE) * DD;
    #pragma unroll
    for (int k = 0; k < TILE*64/128; k++) {
        int i = tid + k*128;
        xs[(i >> 6)*PAD + (i & 63)] = src[i];
    }
    __syncthreads();

    // phase A: per-token LN + logits + softmax
    {
        float4* row = (float4*)(xs + tid*PAD);
        float sum = 0.f, sq = 0.f;
        #pragma unroll
        for (int k = 0; k < 16; k++) {
            float4 v = row[k];
            sum += v.x + v.y + v.z + v.w;
            sq  += v.x*v.x + v.y*v.y + v.z*v.z + v.w*v.w;
        }
        float mean = sum * (1.f/64.f);
        float var  = sq  * (1.f/64.f) - mean*mean;
        float rstd = rsqrtf(var + LN_EPS);

        float lg[SS];
        #pragma unroll
        for (int s = 0; s < SS; s++) lg[s] = 0.f;
        const float4* w4 = (const float4*)lnw;
        const float4* b4 = (const float4*)lnb;
        #pragma unroll
        for (int k = 0; k < 16; k++) {
            float4 v = row[k], w = w4[k], bb = b4[k], n;
            n.x = (v.x - mean)*rstd*w.x + bb.x;
            n.y = (v.y - mean)*rstd*w.y + bb.y;
            n.z = (v.z - mean)*rstd*w.z + bb.z;
            n.w = (v.w - mean)*rstd*w.w + bb.w;
            row[k] = n;
            #pragma unroll
            for (int s = 0; s < SS; s++) {
                float4 qv = ((const float4*)qts[s])[k];
                lg[s] += n.x*qv.x + n.y*qv.y + n.z*qv.z + n.w*qv.w;
            }
        }
        float mx = lg[0];
        #pragma unroll
        for (int s = 1; s < SS; s++) mx = fmaxf(mx, lg[s]);
        float ex[SS], tot = 0.f;
        #pragma unroll
        for (int s = 0; s < SS; s++) { ex[s] = expf(lg[s] - mx); tot += ex[s]; }
        float inv = 1.f / tot;
        #pragma unroll
        for (int s = 0; s < SS; s++) ps[tid][s] = ex[s]*inv + EPSV;
    }
    __syncthreads();

    // phase B: partial u[s][e] = sum_t p[t][s]*xn[t][e], den[s] = sum_t p
    if (tid < 112) {
        int s = tid >> 4, e4 = tid & 15;
        float4 acc = make_float4(0.f, 0.f, 0.f, 0.f);
        #pragma unroll 8
        for (int t = 0; t < TILE; t++) {
            float p = ps[t][s];
            float4 v = *(const float4*)(xs + t*PAD + e4*4);
            acc.x += p*v.x; acc.y += p*v.y; acc.z += p*v.z; acc.w += p*v.w;
        }
        float* up = g_u + (b*SS + s)*DD + e4*4;
        atomicAdd(up + 0, acc.x);
        atomicAdd(up + 1, acc.y);
        atomicAdd(up + 2, acc.z);
        atomicAdd(up + 3, acc.w);
    } else if (tid < 119) {
        int s = tid - 112;
        float dacc = 0.f;
        #pragma unroll 8
        for (int t = 0; t < TILE; t++) dacc += ps[t][s];
        atomicAdd(&g_den[b*SS + s], dacc);
    }
}

// ---------------------------------------------------------------------------
// finalize: gi=(u/den)@C^T ; gh=prev@W_hh^T ; GRU ; LN ; MLP ; residual;
// if not last iter: LN(slots)@M -> qt, zero accumulators.
// grid = B, block = 256, dynamic smem (weights staged with odd pitch).
#define OFF_C    0
#define OFF_WHH  (OFF_C   + 192*65)
#define OFF_W1   (OFF_WHH + 192*65)
#define OFF_W2   (OFF_W1  + 128*65)
#define OFF_UP   (OFF_W2  + 64*129)
#define OFF_PREV (OFF_UP   + SS*64)
#define OFF_GI   (OFF_PREV + SS*64)
#define OFF_GH   (OFF_GI   + SS*192)
#define OFF_ACT  (OFF_GH   + SS*192)
#define OFF_MLN  (OFF_ACT  + SS*64)
#define OFF_H1   (OFF_MLN  + SS*64)
#define OFF_SN   (OFF_H1   + SS*128)
#define SMEM_FL  (OFF_SN   + SS*64)

__global__ void __launch_bounds__(256) k_finalize(
        const float* __restrict__ W_hh,
        const float* __restrict__ b_ih,
        const float* __restrict__ b_hh,
        const float* __restrict__ W1,
        const float* __restrict__ b1,
        const float* __restrict__ W2,
        const float* __restrict__ b2,
        const float* __restrict__ ln_mlp_w,
        const float* __restrict__ ln_mlp_b,
        const float* __restrict__ ln_slots_w,
        const float* __restrict__ ln_slots_b,
        float* __restrict__ out, int last) {
    extern __shared__ float sm[];
    int b = blockIdx.x;
    int tid = threadIdx.x;
    int w = tid >> 5, lane = tid & 31;

    // --- stage weights (coalesced global, odd-pitch smem) ---
    for (int i = tid; i < 192*64; i += 256) sm[OFF_C   + i + (i>>6)] = g_C[i];
    for (int i = tid; i < 192*64; i += 256) sm[OFF_WHH + i + (i>>6)] = W_hh[i];
    for (int i = tid; i < 128*64; i += 256) sm[OFF_W1  + i + (i>>6)] = W1[i];
    for (int i = tid; i < 64*128; i += 256) sm[OFF_W2  + i + (i>>7)] = W2[i];

    // --- stage activations: u' = u/den, prev slots ---
    for (int i = tid; i < SS*64; i += 256) {
        int s = i >> 6;
        float invden = 1.f / g_den[b*SS + s];
        sm[OFF_UP + i]   = g_u[b*SS*64 + i] * invden;
        sm[OFF_PREV + i] = g_slots[b*SS*64 + i];
    }
    __syncthreads();

    // --- gi = u' @ C^T + b_ih ; gh = prev @ W_hh^T + b_hh ---
    for (int i = tid; i < SS*192; i += 256) {
        int s = i / 192, j = i - s*192;
        float ai = b_ih[j], ah = b_hh[j];
        const float* cu = sm + OFF_C   + j*65;
        const float* ch = sm + OFF_WHH + j*65;
        const float* uu = sm + OFF_UP   + s*64;
        const float* pp = sm + OFF_PREV + s*64;
        #pragma unroll 8
        for (int e = 0; e < 64; e++) {
            ai += uu[e] * cu[e];
            ah += pp[e] * ch[e];
        }
        sm[OFF_GI + i] = ai;
        sm[OFF_GH + i] = ah;
    }
    __syncthreads();

    // --- GRU gates -> new slot ---
    for (int i = tid; i < SS*64; i += 256) {
        int s = i >> 6, d = i & 63;
        float gir = sm[OFF_GI + s*192 + d];
        float giz = sm[OFF_GI + s*192 + 64 + d];
        float gin = sm[OFF_GI + s*192 + 128 + d];
        float ghr = sm[OFF_GH + s*192 + d];
        float ghz = sm[OFF_GH + s*192 + 64 + d];
        float ghn = sm[OFF_GH + s*192 + 128 + d];
        float r = 1.f / (1.f + expf(-(gir + ghr)));
        float z = 1.f / (1.f + expf(-(giz + ghz)));
        float n = tanhf(gin + r*ghn);
        sm[OFF_ACT + i] = (1.f - z)*n + z*sm[OFF_PREV + i];
    }
    __syncthreads();

    // --- LN (mlp) per slot, warps 0..6 ---
    if (w < SS) {
        float v0 = sm[OFF_ACT + w*64 + lane], v1 = sm[OFF_ACT + w*64 + lane+32];
        float sum = v0 + v1, sq = v0*v0 + v1*v1;
        #pragma unroll
        for (int o = 16; o; o >>= 1) {
            sum += __shfl_xor_sync(0xffffffffu, sum, o);
            sq  += __shfl_xor_sync(0xffffffffu, sq,  o);
        }
        float mean = sum * (1.f/64.f);
        float var  = sq  * (1.f/64.f) - mean*mean;
        float rstd = rsqrtf(var + LN_EPS);
        sm[OFF_MLN + w*64 + lane]    = (v0 - mean)*rstd*ln_mlp_w[lane]    + ln_mlp_b[lane];
        sm[OFF_MLN + w*64 + lane+32] = (v1 - mean)*rstd*ln_mlp_w[lane+32] + ln_mlp_b[lane+32];
    }
    __syncthreads();

    // --- h1 = relu(mln @ W1^T + b1) ---
    for (int i = tid; i < SS*128; i += 256) {
        int s = i >> 7, j = i & 127;
        float acc = b1[j];
        const float* cw = sm + OFF_W1 + j*65;
        const float* mm = sm + OFF_MLN + s*64;
        #pragma unroll 8
        for (int e = 0; e < 64; e++) acc += mm[e] * cw[e];
        sm[OFF_H1 + i] = fmaxf(acc, 0.f);
    }
    __syncthreads();

    // --- res = newslot + h1 @ W2^T + b2 ---
    for (int i = tid; i < SS*64; i += 256) {
        int s = i >> 6, d = i & 63;
        float acc = b2[d];
        const float* cw = sm + OFF_W2 + d*129;
        const float* hh = sm + OFF_H1 + s*128;
        #pragma unroll 8
        for (int j = 0; j < 128; j++) acc += hh[j] * cw[j];
        float res = sm[OFF_ACT + i] + acc;
        sm[OFF_ACT + i] = res;           // reuse for next-q LN
        g_slots[b*SS*64 + i] = res;
        if (last) out[b*SS*64 + i] = res;
    }
    if (last) return;
    __syncthreads();

    // --- next iteration prep: qt = LN(res) @ M ; zero accumulators ---
    if (w < SS) {
        float v0 = sm[OFF_ACT + w*64 + lane], v1 = sm[OFF_ACT + w*64 + lane+32];
        float sum = v0 + v1, sq = v0*v0 + v1*v1;
        #pragma unroll
        for (int o = 16; o; o >>= 1) {
            sum += __shfl_xor_sync(0xffffffffu, sum, o);
            sq  += __shfl_xor_sync(0xffffffffu, sq,  o);
        }
        float mean = sum * (1.f/64.f);
        float var  = sq  * (1.f/64.f) - mean*mean;
        float rstd = rsqrtf(var + LN_EPS);
        sm[OFF_SN + w*64 + lane]    = (v0 - mean)*rstd*ln_slots_w[lane]    + ln_slots_b[lane];
        sm[OFF_SN + w*64 + lane+32] = (v1 - mean)*rstd*ln_slots_w[lane+32] + ln_slots_b[lane+32];
    }
    for (int i = tid; i < SS*64; i += 256) g_u[b*SS*64 + i] = 0.f;
    if (tid < SS) g_den[b*SS + tid] = 0.f;
    __syncthreads();

    for (int i = tid; i < SS*64; i += 256) {
        int s = i >> 6, tc = i & 63;
        float acc = 0.f;
        const float* ss = sm + OFF_SN + s*64;
        #pragma unroll 8
        for (int e = 0; e < 64; e++) acc += ss[e] * g_M[e*64 + tc];
        g_qt[b*SS*64 + i] = acc;
    }
}

// ---------------------------------------------------------------------------
extern "C" void kernel_launch(void* const* d_in, const int* in_sizes, int n_in,
                              void* d_out, int out_size) {
    const float* inputs     = (const float*)d_in[0];
    const float* noise      = (const float*)d_in[1];
    const float* ln_in_w    = (const float*)d_in[2];
    const float* ln_in_b    = (const float*)d_in[3];
    const float* ln_slots_w = (const float*)d_in[4];
    const float* ln_slots_b = (const float*)d_in[5];
    const float* ln_mlp_w   = (const float*)d_in[6];
    const float* ln_mlp_b   = (const float*)d_in[7];
    const float* mu         = (const float*)d_in[8];
    const float* logsig     = (const float*)d_in[9];
    const float* Wq         = (const float*)d_in[10];
    const float* Wk         = (const float*)d_in[11];
    const float* Wv         = (const float*)d_in[12];
    const float* W_ih       = (const float*)d_in[13];
    const float* W_hh       = (const float*)d_in[14];
    const float* b_ih       = (const float*)d_in[15];
    const float* b_hh       = (const float*)d_in[16];
    const float* W1         = (const float*)d_in[17];
    const float* b1         = (const float*)d_in[18];
    const float* W2         = (const float*)d_in[19];
    const float* b2         = (const float*)d_in[20];
    float* out = (float*)d_out;

    static_assert(SMEM_FL*4 < 227*1024, "smem overflow");
    cudaFuncSetAttribute(k_finalize, cudaFuncAttributeMaxDynamicSharedMemorySize,
                         SMEM_FL*4);

    k_init_slots<<<(BB*SS*DD + 255)/256, 256>>>(noise, mu, logsig);
    k_precomp<<<64, 256>>>(Wq, Wk, W_ih, Wv);
    k_q0<<<BB, 256>>>(ln_slots_w, ln_slots_b);
    for (int it = 0; it < NUM_ITERS; it++) {
        dim3 grid(NN/TILE, BB);
        k_attn<<<grid, 128>>>(inputs, ln_in_w, ln_in_b);
        k_finalize<<<BB, 256, SMEM_FL*4>>>(W_hh, b_ih, b_hh, W1, b1, W2, b2,
                                           ln_mlp_w, ln_mlp_b,
                                           ln_slots_w, ln_slots_b,
                                           out, it == NUM_ITERS - 1 ? 1 : 0);
    }
}